// round 1
// baseline (speedup 1.0000x reference)
#include <cuda_runtime.h>
#include <math.h>

// ---------------------------------------------------------------------------
// DynamicMemoryBank: x[64,1024,256], memory[1,1024,256]
//   energy = x @ mem^T            [65536,1024]
//   weights = softmax(energy)
//   retrieved = weights @ mem     [65536,256]
//   cat = [x, retrieved]          [65536,512]   -> output part 1
//   h = silu(cat @ w1 + b1)       [65536,1024]
//   g = sigmoid(h @ w2 + b2)      [65536,256]
//   xmean = mean_t x              [64,256]
//   new_memory[m,c] = mean_b( mem[m,c]*(1-g[b,m,c]) + xmean[b,c]*g[b,m,c] )
//                                  [1024,256]   -> output part 2
// ---------------------------------------------------------------------------

// scratch (device globals: allocation-free rule)
__device__ float g_scr1[67108864];  // 256MB: energy/weights, then h
__device__ float g_scr2[16777216];  //  64MB: gate
__device__ float g_xmean[16384];    // [64,256]

// ---------------------------------------------------------------------------
// Generic fp32 SGEMM: C[M x N] = A[M x K] * B  (+ bias, + activation)
// BM=128, BN=128, BK=16, 256 threads, 8x8 per thread.
// TRANSB: B is [N,K] row-major (both operands K-contiguous).
// EPI: 0 = none, 1 = silu(v + bias), 2 = sigmoid(v + bias)
// All dims are multiples of tile sizes for this problem -> no bounds checks.
// ---------------------------------------------------------------------------
template<int EPI, bool TRANSB>
__global__ void __launch_bounds__(256)
sgemm128(const float* __restrict__ A, const float* __restrict__ B,
         const float* __restrict__ bias, float* __restrict__ C,
         int K, int lda, int ldb, int ldc, int c_off)
{
    constexpr int BM = 128, BN = 128, BK = 16;
    __shared__ float As[BK][BM + 4];
    __shared__ float Bs[BK][BN + 4];

    const int tid = threadIdx.x;
    const long row0 = (long)blockIdx.y * BM;
    const int  col0 = blockIdx.x * BN;
    const int tx = tid & 15;        // N direction
    const int ty = tid >> 4;        // M direction

    float acc[8][8];
#pragma unroll
    for (int i = 0; i < 8; i++)
#pragma unroll
        for (int j = 0; j < 8; j++) acc[i][j] = 0.0f;

    // loader indices (K-contiguous loads, 2 float4 per thread)
    const int lr  = tid >> 2;        // 0..63
    const int lc4 = (tid & 3) << 2;  // 0,4,8,12
    // NN B loader (N-contiguous)
    const int bnr  = tid >> 5;        // 0..7
    const int bnc4 = (tid & 31) << 2; // 0..124

    const float* Aptr = A + row0 * lda;

    for (int k0 = 0; k0 < K; k0 += BK) {
        // ---- load A tile (transposed store into As[k][m]) ----
#pragma unroll
        for (int r = 0; r < 2; r++) {
            int rr = lr + r * 64;
            float4 v = *(const float4*)(Aptr + (long)rr * lda + k0 + lc4);
            As[lc4 + 0][rr] = v.x;
            As[lc4 + 1][rr] = v.y;
            As[lc4 + 2][rr] = v.z;
            As[lc4 + 3][rr] = v.w;
        }
        // ---- load B tile ----
        if (TRANSB) {
#pragma unroll
            for (int r = 0; r < 2; r++) {
                int rr = lr + r * 64;   // n index within tile
                float4 v = *(const float4*)(B + (long)(col0 + rr) * ldb + k0 + lc4);
                Bs[lc4 + 0][rr] = v.x;
                Bs[lc4 + 1][rr] = v.y;
                Bs[lc4 + 2][rr] = v.z;
                Bs[lc4 + 3][rr] = v.w;
            }
        } else {
#pragma unroll
            for (int r = 0; r < 2; r++) {
                int rr = bnr + r * 8;   // k index within tile
                float4 v = *(const float4*)(B + (long)(k0 + rr) * ldb + col0 + bnc4);
                *(float4*)&Bs[rr][bnc4] = v;
            }
        }
        __syncthreads();

#pragma unroll
        for (int kk = 0; kk < BK; kk++) {
            float a[8], b[8];
            *(float4*)&a[0] = *(const float4*)&As[kk][ty * 8];
            *(float4*)&a[4] = *(const float4*)&As[kk][ty * 8 + 4];
            *(float4*)&b[0] = *(const float4*)&Bs[kk][tx * 8];
            *(float4*)&b[4] = *(const float4*)&Bs[kk][tx * 8 + 4];
#pragma unroll
            for (int i = 0; i < 8; i++)
#pragma unroll
                for (int j = 0; j < 8; j++)
                    acc[i][j] = fmaf(a[i], b[j], acc[i][j]);
        }
        __syncthreads();
    }

    // ---- epilogue ----
#pragma unroll
    for (int i = 0; i < 8; i++) {
        long r = row0 + ty * 8 + i;
        float* Crow = C + r * ldc + c_off + col0 + tx * 8;
#pragma unroll
        for (int j = 0; j < 8; j++) {
            float v = acc[i][j];
            if (EPI == 1) {
                v += bias[col0 + tx * 8 + j];
                v = v / (1.0f + __expf(-v));       // silu
            } else if (EPI == 2) {
                v += bias[col0 + tx * 8 + j];
                v = 1.0f / (1.0f + __expf(-v));    // sigmoid
            }
            Crow[j] = v;
        }
    }
}

// ---------------------------------------------------------------------------
// Row softmax, in place. One block (256 threads) per row of length N.
// ---------------------------------------------------------------------------
__global__ void softmax_row(float* __restrict__ data, int N)
{
    float* p = data + (long)blockIdx.x * N;
    const int tid = threadIdx.x;
    __shared__ float red[8];

    float m = -3.4e38f;
    for (int i = tid; i < N; i += 256) m = fmaxf(m, p[i]);
#pragma unroll
    for (int o = 16; o; o >>= 1) m = fmaxf(m, __shfl_xor_sync(0xffffffffu, m, o));
    if ((tid & 31) == 0) red[tid >> 5] = m;
    __syncthreads();
    float mb = red[0];
#pragma unroll
    for (int w = 1; w < 8; w++) mb = fmaxf(mb, red[w]);
    __syncthreads();

    float s = 0.0f;
    for (int i = tid; i < N; i += 256) {
        float e = __expf(p[i] - mb);
        p[i] = e;
        s += e;
    }
#pragma unroll
    for (int o = 16; o; o >>= 1) s += __shfl_xor_sync(0xffffffffu, s, o);
    if ((tid & 31) == 0) red[tid >> 5] = s;
    __syncthreads();
    float sb = 0.0f;
#pragma unroll
    for (int w = 0; w < 8; w++) sb += red[w];
    float inv = 1.0f / sb;
    for (int i = tid; i < N; i += 256) p[i] *= inv;
}

// ---------------------------------------------------------------------------
// Copy x[65536,256] into cat[65536,512] columns 0..255 (float4 version).
// ---------------------------------------------------------------------------
__global__ void copy_x_to_cat(const float4* __restrict__ x, float4* __restrict__ cat)
{
    long i = (long)blockIdx.x * blockDim.x + threadIdx.x;  // over 65536*64 float4
    long rowq = i >> 6;     // 64 float4 per x row
    long cq = i & 63;
    cat[rowq * 128 + cq] = x[i];
}

// ---------------------------------------------------------------------------
// xmean[b,c] = mean_t x[b,t,c]
// ---------------------------------------------------------------------------
__global__ void xmean_kernel(const float* __restrict__ x, float* __restrict__ xm)
{
    int b = blockIdx.x;
    int c = threadIdx.x;  // 256
    const float* p = x + (long)b * 1024 * 256 + c;
    float s = 0.0f;
    for (int t = 0; t < 1024; t++) s += p[t * 256];
    xm[b * 256 + c] = s * (1.0f / 1024.0f);
}

// ---------------------------------------------------------------------------
// new_memory[m,c] = mean_b( mem[m,c] + (xmean[b,c]-mem[m,c]) * g[b,m,c] )
// idx = m*256 + c, g laid out [b, m, c].
// ---------------------------------------------------------------------------
__global__ void newmem_kernel(const float* __restrict__ mem, const float* __restrict__ g,
                              const float* __restrict__ xm, float* __restrict__ outp)
{
    int idx = blockIdx.x * 256 + threadIdx.x;  // 0..262143
    int c = idx & 255;
    float mm = mem[idx];
    float s = 0.0f;
#pragma unroll 4
    for (int b = 0; b < 64; b++) {
        float gg = g[(long)b * 262144 + idx];
        s += mm + (xm[b * 256 + c] - mm) * gg;
    }
    outp[idx] = s * (1.0f / 64.0f);
}

// ---------------------------------------------------------------------------
extern "C" void kernel_launch(void* const* d_in, const int* in_sizes, int n_in,
                              void* d_out, int out_size)
{
    const float* x      = (const float*)d_in[0];
    const float* memory = (const float*)d_in[1];
    const float* w1     = (const float*)d_in[2];
    const float* b1     = (const float*)d_in[3];
    const float* w2     = (const float*)d_in[4];
    const float* b2     = (const float*)d_in[5];

    float* out    = (float*)d_out;
    float* cat    = out;                       // [65536, 512]
    float* newmem = out + 33554432ll;          // [1024, 256]

    float *scr1, *scr2, *xm;
    cudaGetSymbolAddress((void**)&scr1, g_scr1);
    cudaGetSymbolAddress((void**)&scr2, g_scr2);
    cudaGetSymbolAddress((void**)&xm,   g_xmean);

    const int MROWS = 65536;
    dim3 blk(256);

    // G1: energy = x @ mem^T  -> scr1 [65536,1024]
    sgemm128<0, true><<<dim3(1024 / 128, MROWS / 128), blk>>>(
        x, memory, nullptr, scr1, /*K=*/256, /*lda=*/256, /*ldb=*/256, /*ldc=*/1024, 0);

    // softmax rows of 1024, in place
    softmax_row<<<MROWS, 256>>>(scr1, 1024);

    // cat[:, 0:256] = x
    copy_x_to_cat<<<(MROWS * 64) / 256, 256>>>((const float4*)x, (float4*)cat);

    // G2: retrieved = weights @ mem -> cat[:, 256:512]
    sgemm128<0, false><<<dim3(256 / 128, MROWS / 128), blk>>>(
        scr1, memory, nullptr, cat, /*K=*/1024, /*lda=*/1024, /*ldb=*/256, /*ldc=*/512, 256);

    // G3: h = silu(cat @ w1 + b1) -> scr1 [65536,1024] (reuse)
    sgemm128<1, false><<<dim3(1024 / 128, MROWS / 128), blk>>>(
        cat, w1, b1, scr1, /*K=*/512, /*lda=*/512, /*ldb=*/1024, /*ldc=*/1024, 0);

    // G4: g = sigmoid(h @ w2 + b2) -> scr2 [65536,256]
    sgemm128<2, false><<<dim3(256 / 128, MROWS / 128), blk>>>(
        scr1, w2, b2, scr2, /*K=*/1024, /*lda=*/1024, /*ldb=*/256, /*ldc=*/256, 0);

    // xmean over T
    xmean_kernel<<<64, 256>>>(x, xm);

    // memory blend + batch mean
    newmem_kernel<<<1024, 256>>>(memory, scr2, xm, newmem);
}

// round 3
// speedup vs baseline: 6.4455x; 6.4455x over previous
#include <cuda_runtime.h>
#include <cuda_bf16.h>
#include <cstdint>
#include <math.h>

// ===========================================================================
// DynamicMemoryBank via mma.sync (bf16 HMMA, fp32 accum) — plain sm_103 legal
//   energy = x @ mem^T         (G1)  -> bf16
//   weights = softmax(energy)        (in place, bf16)
//   retrieved = weights @ memT^T (G2)-> cat fp32 (out) + catb bf16
//   h = silu(catb @ w1T^T + b1) (G3) -> bf16
//   g = sigmoid(hb @ w2T^T + b2)(G4) -> fp32
//   newmem = mean_b blend            -> out
// All GEMMs: C = A[M,K] @ B[N,K]^T, A/B K-major bf16.
// ===========================================================================

__device__ __forceinline__ uint32_t smem_u32(const void* p) {
    uint32_t a;
    asm("{ .reg .u64 t; cvta.to.shared.u64 t, %1; cvt.u32.u64 %0, t; }" : "=r"(a) : "l"(p));
    return a;
}

#define LDSM_X4(R0, R1, R2, R3, ADDR) \
    asm volatile("ldmatrix.sync.aligned.m8n8.x4.shared.b16 {%0,%1,%2,%3}, [%4];" \
        : "=r"(R0), "=r"(R1), "=r"(R2), "=r"(R3) : "r"(ADDR))

#define MMA16816(C, A0, A1, A2, A3, B0, B1) \
    asm volatile("mma.sync.aligned.m16n8k16.row.col.f32.bf16.bf16.f32 " \
        "{%0,%1,%2,%3}, {%4,%5,%6,%7}, {%8,%9}, {%0,%1,%2,%3};" \
        : "+f"((C)[0]), "+f"((C)[1]), "+f"((C)[2]), "+f"((C)[3]) \
        : "r"(A0), "r"(A1), "r"(A2), "r"(A3), "r"(B0), "r"(B1))

#define CP_ASYNC16(DST, SRC) \
    asm volatile("cp.async.cg.shared.global [%0], [%1], 16;" :: "r"(DST), "l"(SRC))
#define CP_COMMIT() asm volatile("cp.async.commit_group;" ::: "memory")
#define CP_WAIT(N)  asm volatile("cp.async.wait_group %0;" :: "n"(N) : "memory")

// ---------------------------------------------------------------------------
// scratch (device globals)
// ---------------------------------------------------------------------------
__device__ __nv_bfloat16 g_xb[16777216];      // [65536,256]
__device__ __nv_bfloat16 g_energy[67108864];  // [65536,1024] energy -> weights
__device__ __nv_bfloat16 g_catb[33554432];    // [65536,512]
__device__ __nv_bfloat16 g_hb[67108864];      // [65536,1024]
__device__ float         g_gate[16777216];    // [65536,256]
__device__ __nv_bfloat16 g_memb[262144];      // [1024,256]
__device__ __nv_bfloat16 g_membT[262144];     // [256,1024]
__device__ __nv_bfloat16 g_w1T[524288];       // [1024,512]
__device__ __nv_bfloat16 g_w2T[262144];       // [256,1024]
__device__ float         g_xmean[16384];      // [64,256]

// ---------------------------------------------------------------------------
// bf16 GEMM: BM=128, BN=128, BK=64, 256 thr, 8 warps (warp tile 32x64).
// smem tiles: 128 rows x 128B, SW128-swizzled (16B chunk ^= row&7).
// EPI: 0 = bf16 -> Cb
//      1 = fp32 -> Cf AND bf16 -> Cb
//      2 = silu(v+bias)    -> bf16 Cb
//      3 = sigmoid(v+bias) -> fp32 Cf
// ---------------------------------------------------------------------------
template<int EPI>
__global__ void __launch_bounds__(256, 2)
gemm_mma(const __nv_bfloat16* __restrict__ A, const __nv_bfloat16* __restrict__ B,
         const float* __restrict__ bias, float* __restrict__ Cf,
         __nv_bfloat16* __restrict__ Cb, int K, int ldcf, int ldcb, int c_off)
{
    extern __shared__ char dsm[];
    const uint32_t sbase = (smem_u32(dsm) + 1023) & ~1023u;
    const int tid = threadIdx.x;
    const int wid = tid >> 5, lane = tid & 31;
    const int wm = wid & 3;          // 32-row block
    const int wn = wid >> 2;         // 64-col block
    const long row0 = (long)blockIdx.y * 128;
    const long col0 = (long)blockIdx.x * 128;

    const uint32_t sA[2] = { sbase,         sbase + 32768 };
    const uint32_t sB[2] = { sbase + 16384, sbase + 49152 };

    float acc[2][8][4];
#pragma unroll
    for (int i = 0; i < 2; i++)
#pragma unroll
        for (int j = 0; j < 8; j++)
#pragma unroll
            for (int q = 0; q < 4; q++) acc[i][j][q] = 0.0f;

    const char* Ag = (const char*)(A + row0 * K);
    const char* Bg = (const char*)(B + col0 * K);
    const long rowb = (long)K * 2;

    // per-thread loader coords: 4 chunks of A + 4 of B per k-chunk
    const int lr = tid >> 3;         // row/8-chunk base: idx = tid + j*256
    const int lc = tid & 7;

    const int nchunks = K >> 6;

    // prologue: chunk 0
    {
#pragma unroll
        for (int j = 0; j < 4; j++) {
            int r = lr + j * 32;
            uint32_t off = (uint32_t)(r * 128) + (uint32_t)((lc ^ (r & 7)) << 4);
            CP_ASYNC16(sA[0] + off, Ag + (long)r * rowb + lc * 16);
            CP_ASYNC16(sB[0] + off, Bg + (long)r * rowb + lc * 16);
        }
        CP_COMMIT();
    }

    for (int i = 0; i < nchunks; i++) {
        const int b = i & 1;
        if (i + 1 < nchunks) {
            const long kb = (long)(i + 1) << 7;  // byte offset of next chunk
#pragma unroll
            for (int j = 0; j < 4; j++) {
                int r = lr + j * 32;
                uint32_t off = (uint32_t)(r * 128) + (uint32_t)((lc ^ (r & 7)) << 4);
                CP_ASYNC16(sA[1 - b] + off, Ag + (long)r * rowb + kb + lc * 16);
                CP_ASYNC16(sB[1 - b] + off, Bg + (long)r * rowb + kb + lc * 16);
            }
            CP_COMMIT();
            CP_WAIT(1);
        } else {
            CP_WAIT(0);
        }
        __syncthreads();

#pragma unroll
        for (int ks = 0; ks < 4; ks++) {
            uint32_t af[2][4];
#pragma unroll
            for (int mi = 0; mi < 2; mi++) {
                int r = wm * 32 + mi * 16 + (lane & 15);
                int cch = ks * 2 + (lane >> 4);
                uint32_t addr = sA[b] + (uint32_t)(r * 128) + (uint32_t)((cch ^ (r & 7)) << 4);
                LDSM_X4(af[mi][0], af[mi][1], af[mi][2], af[mi][3], addr);
            }
            uint32_t bf[4][4];
#pragma unroll
            for (int nt = 0; nt < 4; nt++) {
                int r = wn * 64 + nt * 16 + (lane & 7) + ((lane >> 4) << 3);
                int cch = ks * 2 + ((lane >> 3) & 1);
                uint32_t addr = sB[b] + (uint32_t)(r * 128) + (uint32_t)((cch ^ (r & 7)) << 4);
                LDSM_X4(bf[nt][0], bf[nt][1], bf[nt][2], bf[nt][3], addr);
            }
#pragma unroll
            for (int mi = 0; mi < 2; mi++)
#pragma unroll
                for (int ni = 0; ni < 8; ni++) {
                    uint32_t b0 = bf[ni >> 1][(ni & 1) * 2];
                    uint32_t b1 = bf[ni >> 1][(ni & 1) * 2 + 1];
                    MMA16816(acc[mi][ni], af[mi][0], af[mi][1], af[mi][2], af[mi][3], b0, b1);
                }
        }
        __syncthreads();
    }

    // ---- epilogue ----
#pragma unroll
    for (int mi = 0; mi < 2; mi++) {
#pragma unroll
        for (int h = 0; h < 2; h++) {
            long r = row0 + wm * 32 + mi * 16 + (lane >> 2) + h * 8;
#pragma unroll
            for (int ni = 0; ni < 8; ni++) {
                int cn = (int)col0 + wn * 64 + ni * 8 + (lane & 3) * 2;
                float v0 = acc[mi][ni][h * 2];
                float v1 = acc[mi][ni][h * 2 + 1];
                if (EPI == 2 || EPI == 3) {
                    v0 += bias[cn];
                    v1 += bias[cn + 1];
                    if (EPI == 2) {
                        v0 = v0 / (1.0f + __expf(-v0));
                        v1 = v1 / (1.0f + __expf(-v1));
                    } else {
                        v0 = 1.0f / (1.0f + __expf(-v0));
                        v1 = 1.0f / (1.0f + __expf(-v1));
                    }
                }
                if (EPI == 0 || EPI == 1 || EPI == 2) {
                    __nv_bfloat162 h2 = __float22bfloat162_rn(make_float2(v0, v1));
                    *(uint32_t*)(Cb + r * ldcb + c_off + cn) = *reinterpret_cast<uint32_t*>(&h2);
                }
                if (EPI == 1 || EPI == 3) {
                    *(float2*)(Cf + r * ldcf + c_off + cn) = make_float2(v0, v1);
                }
            }
        }
    }
}

// ---------------------------------------------------------------------------
// softmax over rows of 1024 bf16, in place. 256 threads/row.
// ---------------------------------------------------------------------------
__global__ void softmax_bf16(__nv_bfloat16* __restrict__ d)
{
    __nv_bfloat162* p = (__nv_bfloat162*)(d + (long)blockIdx.x * 1024);
    const int tid = threadIdx.x;
    __shared__ float red[8];

    __nv_bfloat162 v0 = p[tid], v1 = p[tid + 256];
    float a0 = __bfloat162float(v0.x), a1 = __bfloat162float(v0.y);
    float a2 = __bfloat162float(v1.x), a3 = __bfloat162float(v1.y);

    float m = fmaxf(fmaxf(a0, a1), fmaxf(a2, a3));
#pragma unroll
    for (int o = 16; o; o >>= 1) m = fmaxf(m, __shfl_xor_sync(0xffffffffu, m, o));
    if ((tid & 31) == 0) red[tid >> 5] = m;
    __syncthreads();
    float mb = red[0];
#pragma unroll
    for (int w = 1; w < 8; w++) mb = fmaxf(mb, red[w]);
    __syncthreads();

    float e0 = __expf(a0 - mb), e1 = __expf(a1 - mb);
    float e2 = __expf(a2 - mb), e3 = __expf(a3 - mb);
    float s = e0 + e1 + e2 + e3;
#pragma unroll
    for (int o = 16; o; o >>= 1) s += __shfl_xor_sync(0xffffffffu, s, o);
    if ((tid & 31) == 0) red[tid >> 5] = s;
    __syncthreads();
    float sb = 0.0f;
#pragma unroll
    for (int w = 0; w < 8; w++) sb += red[w];
    float inv = 1.0f / sb;

    p[tid]       = __float22bfloat162_rn(make_float2(e0 * inv, e1 * inv));
    p[tid + 256] = __float22bfloat162_rn(make_float2(e2 * inv, e3 * inv));
}

// ---------------------------------------------------------------------------
// conversions
// ---------------------------------------------------------------------------
__global__ void convert_x(const float4* __restrict__ x4, float4* __restrict__ cat4,
                          uint2* __restrict__ xb2, uint2* __restrict__ catb2)
{
    long i = (long)blockIdx.x * 256 + threadIdx.x;  // over 65536*64 float4
    long row = i >> 6;
    long c4 = i & 63;
    float4 v = x4[i];
    cat4[row * 128 + c4] = v;
    __nv_bfloat162 l = __float22bfloat162_rn(make_float2(v.x, v.y));
    __nv_bfloat162 h = __float22bfloat162_rn(make_float2(v.z, v.w));
    uint2 pk = make_uint2(*reinterpret_cast<uint32_t*>(&l), *reinterpret_cast<uint32_t*>(&h));
    xb2[i] = pk;
    catb2[row * 128 + c4] = pk;
}

__global__ void conv_mem(const float* __restrict__ mem,
                         __nv_bfloat16* __restrict__ memb, __nv_bfloat16* __restrict__ memT)
{
    int m = blockIdx.x, c = threadIdx.x;
    float v = mem[m * 256 + c];
    __nv_bfloat16 b = __float2bfloat16(v);
    memb[m * 256 + c] = b;
    memT[c * 1024 + m] = b;
}

__global__ void conv_w1(const float* __restrict__ w1, __nv_bfloat16* __restrict__ w1T)
{
    int i = blockIdx.x * 256 + threadIdx.x;  // 524288
    int k = i >> 10, n = i & 1023;
    w1T[n * 512 + k] = __float2bfloat16(w1[i]);
}

__global__ void conv_w2(const float* __restrict__ w2, __nv_bfloat16* __restrict__ w2T)
{
    int i = blockIdx.x * 256 + threadIdx.x;  // 262144
    int f = i >> 8, c = i & 255;
    w2T[c * 1024 + f] = __float2bfloat16(w2[i]);
}

// ---------------------------------------------------------------------------
__global__ void xmean_kernel(const float* __restrict__ x, float* __restrict__ xm)
{
    int b = blockIdx.x, c = threadIdx.x;
    const float* p = x + (long)b * 1024 * 256 + c;
    float s = 0.0f;
    for (int t = 0; t < 1024; t++) s += p[t * 256];
    xm[b * 256 + c] = s * (1.0f / 1024.0f);
}

__global__ void newmem_kernel(const float* __restrict__ mem, const float* __restrict__ g,
                              const float* __restrict__ xm, float* __restrict__ outp)
{
    int idx = blockIdx.x * 256 + threadIdx.x;
    int c = idx & 255;
    float mm = mem[idx];
    float s = 0.0f;
#pragma unroll 4
    for (int b = 0; b < 64; b++) {
        float gg = g[(long)b * 262144 + idx];
        s += mm + (xm[b * 256 + c] - mm) * gg;
    }
    outp[idx] = s * (1.0f / 64.0f);
}

// ---------------------------------------------------------------------------
extern "C" void kernel_launch(void* const* d_in, const int* in_sizes, int n_in,
                              void* d_out, int out_size)
{
    const float* x      = (const float*)d_in[0];
    const float* memory = (const float*)d_in[1];
    const float* w1     = (const float*)d_in[2];
    const float* b1     = (const float*)d_in[3];
    const float* w2     = (const float*)d_in[4];
    const float* b2     = (const float*)d_in[5];

    float* out    = (float*)d_out;
    float* cat    = out;               // [65536,512]
    float* newmem = out + 33554432ll;  // [1024,256]

    __nv_bfloat16 *xb, *energy, *catb, *hb, *memb, *memT, *w1T, *w2T;
    float *gate, *xm;
    cudaGetSymbolAddress((void**)&xb, g_xb);
    cudaGetSymbolAddress((void**)&energy, g_energy);
    cudaGetSymbolAddress((void**)&catb, g_catb);
    cudaGetSymbolAddress((void**)&hb, g_hb);
    cudaGetSymbolAddress((void**)&gate, g_gate);
    cudaGetSymbolAddress((void**)&memb, g_memb);
    cudaGetSymbolAddress((void**)&memT, g_membT);
    cudaGetSymbolAddress((void**)&w1T, g_w1T);
    cudaGetSymbolAddress((void**)&w2T, g_w2T);
    cudaGetSymbolAddress((void**)&xm, g_xmean);

    const int SMEM = 1024 + 65536;  // align guard + 2x(16KB A + 16KB B)
    cudaFuncSetAttribute(gemm_mma<0>, cudaFuncAttributeMaxDynamicSharedMemorySize, SMEM);
    cudaFuncSetAttribute(gemm_mma<1>, cudaFuncAttributeMaxDynamicSharedMemorySize, SMEM);
    cudaFuncSetAttribute(gemm_mma<2>, cudaFuncAttributeMaxDynamicSharedMemorySize, SMEM);
    cudaFuncSetAttribute(gemm_mma<3>, cudaFuncAttributeMaxDynamicSharedMemorySize, SMEM);

    // conversions
    convert_x<<<16384, 256>>>((const float4*)x, (float4*)cat, (uint2*)xb, (uint2*)catb);
    conv_mem<<<1024, 256>>>(memory, memb, memT);
    conv_w1<<<2048, 256>>>(w1, w1T);
    conv_w2<<<1024, 256>>>(w2, w2T);

    // G1: energy = xb @ memb^T   [65536,1024] bf16
    gemm_mma<0><<<dim3(8, 512), 256, SMEM>>>(xb, memb, nullptr, nullptr, energy, 256, 0, 1024, 0);

    // softmax in place -> weights bf16
    softmax_bf16<<<65536, 256>>>(energy);

    // G2: retrieved = weights @ memT^T -> cat[:,256:512] fp32 + catb[:,256:512] bf16
    gemm_mma<1><<<dim3(2, 512), 256, SMEM>>>(energy, memT, nullptr, cat, catb, 1024, 512, 512, 256);

    // G3: h = silu(catb @ w1T^T + b1) -> hb bf16 [65536,1024]
    gemm_mma<2><<<dim3(8, 512), 256, SMEM>>>(catb, w1T, b1, nullptr, hb, 512, 0, 1024, 0);

    // G4: g = sigmoid(hb @ w2T^T + b2) -> gate fp32 [65536,256]
    gemm_mma<3><<<dim3(2, 512), 256, SMEM>>>(hb, w2T, b2, gate, nullptr, 1024, 256, 0, 0);

    // reductions
    xmean_kernel<<<64, 256>>>(x, xm);
    newmem_kernel<<<1024, 256>>>(memory, gate, xm, newmem);
}

// round 4
// speedup vs baseline: 7.1543x; 1.1100x over previous
#include <cuda_runtime.h>
#include <cuda_bf16.h>
#include <cstdint>
#include <math.h>

// ===========================================================================
// DynamicMemoryBank — R4: flash-fused attention (G1+softmax+G2) + HMMA GEMMs
//   flash:  retrieved = softmax(x@mem^T)@mem  -> cat fp32 + catb bf16 (fused)
//   G3: h = silu(catb @ w1T^T + b1) -> bf16
//   G4: g = sigmoid(hb @ w2T^T + b2)-> fp32
//   newmem = mean_b blend -> out
// ===========================================================================

__device__ __forceinline__ uint32_t smem_u32(const void* p) {
    uint32_t a;
    asm("{ .reg .u64 t; cvta.to.shared.u64 t, %1; cvt.u32.u64 %0, t; }" : "=r"(a) : "l"(p));
    return a;
}

#define LDSM_X4(R0, R1, R2, R3, ADDR) \
    asm volatile("ldmatrix.sync.aligned.m8n8.x4.shared.b16 {%0,%1,%2,%3}, [%4];" \
        : "=r"(R0), "=r"(R1), "=r"(R2), "=r"(R3) : "r"(ADDR))

#define LDSM_X4T(R0, R1, R2, R3, ADDR) \
    asm volatile("ldmatrix.sync.aligned.m8n8.x4.trans.shared.b16 {%0,%1,%2,%3}, [%4];" \
        : "=r"(R0), "=r"(R1), "=r"(R2), "=r"(R3) : "r"(ADDR))

#define MMA16816(C, A0, A1, A2, A3, B0, B1) \
    asm volatile("mma.sync.aligned.m16n8k16.row.col.f32.bf16.bf16.f32 " \
        "{%0,%1,%2,%3}, {%4,%5,%6,%7}, {%8,%9}, {%0,%1,%2,%3};" \
        : "+f"((C)[0]), "+f"((C)[1]), "+f"((C)[2]), "+f"((C)[3]) \
        : "r"(A0), "r"(A1), "r"(A2), "r"(A3), "r"(B0), "r"(B1))

#define CP_ASYNC16(DST, SRC) \
    asm volatile("cp.async.cg.shared.global [%0], [%1], 16;" :: "r"(DST), "l"(SRC))
#define CP_COMMIT() asm volatile("cp.async.commit_group;" ::: "memory")
#define CP_WAIT(N)  asm volatile("cp.async.wait_group %0;" :: "n"(N) : "memory")

// ---------------------------------------------------------------------------
// scratch
// ---------------------------------------------------------------------------
__device__ __nv_bfloat16 g_xb[16777216];      // [65536,256]
__device__ __nv_bfloat16 g_catb[33554432];    // [65536,512]
__device__ __nv_bfloat16 g_hb[67108864];      // [65536,1024]
__device__ float         g_gate[16777216];    // [65536,256]
__device__ __nv_bfloat16 g_memb[262144];      // [1024,256]
__device__ __nv_bfloat16 g_w1T[524288];       // [1024,512]
__device__ __nv_bfloat16 g_w2T[262144];       // [256,1024]
__device__ float         g_xmean[16384];      // [64,256]

// swizzled addr within a 128-row x 512B tile
__device__ __forceinline__ uint32_t tile_addr(uint32_t base, int r, int colbyte) {
    return base + (uint32_t)(r * 512) + (uint32_t)(colbyte & ~127)
         + (uint32_t)(((((colbyte >> 4) & 7) ^ (r & 7)) << 4));
}

// ---------------------------------------------------------------------------
// Flash kernel: per CTA 128 rows of x; loop 8 chunks of 128 mem rows.
// 256 threads, 8 warps; warp w owns rows 16w..16w+15 (full S width 128).
// ---------------------------------------------------------------------------
__global__ void __launch_bounds__(256, 1)
flash_attn(const __nv_bfloat16* __restrict__ xb, const __nv_bfloat16* __restrict__ memb,
           float* __restrict__ cat, __nv_bfloat16* __restrict__ catb)
{
    extern __shared__ char dsm[];
    const uint32_t sbase = (smem_u32(dsm) + 1023) & ~1023u;
    const uint32_t xs = sbase;
    const uint32_t ms[2] = { sbase + 65536, sbase + 131072 };

    const int tid = threadIdx.x;
    const int wid = tid >> 5, lane = tid & 31;
    const long row0 = (long)blockIdx.x * 128;

    // ---- loaders: 16 chunks of 16B per thread per 64KB tile ----
    const int lr = tid >> 1;          // 0..127 row pairs? use: idx = tid + j*256
    (void)lr;
    // x tile load (rows of 512B): idx over 4096 16B-chunks
    {
        const char* Xg = (const char*)(xb + row0 * 256);
#pragma unroll
        for (int j = 0; j < 16; j++) {
            int idx = tid + j * 256;          // 0..4095
            int r = idx >> 5;                 // row (32 chunks/row)
            int s = idx & 31;                 // 16B chunk in row
            int colbyte = s << 4;
            CP_ASYNC16(tile_addr(xs, r, colbyte), Xg + (long)r * 512 + colbyte);
        }
        CP_COMMIT();
    }
    // mem chunk 0
    {
        const char* Mg = (const char*)memb;
#pragma unroll
        for (int j = 0; j < 16; j++) {
            int idx = tid + j * 256;
            int r = idx >> 5;
            int colbyte = (idx & 31) << 4;
            CP_ASYNC16(tile_addr(ms[0], r, colbyte), Mg + (long)r * 512 + colbyte);
        }
        CP_COMMIT();
    }

    float acc_o[32][4];
#pragma unroll
    for (int b = 0; b < 32; b++)
#pragma unroll
        for (int q = 0; q < 4; q++) acc_o[b][q] = 0.0f;
    float m0 = -1e30f, m1 = -1e30f, l0 = 0.0f, l1 = 0.0f;

    for (int c = 0; c < 8; c++) {
        const int b = c & 1;
        if (c + 1 < 8) {
            const char* Mg = (const char*)(memb + (long)(c + 1) * 128 * 256);
#pragma unroll
            for (int j = 0; j < 16; j++) {
                int idx = tid + j * 256;
                int r = idx >> 5;
                int colbyte = (idx & 31) << 4;
                CP_ASYNC16(tile_addr(ms[1 - b], r, colbyte), Mg + (long)r * 512 + colbyte);
            }
            CP_COMMIT();
            CP_WAIT(1);
        } else {
            CP_WAIT(0);
        }
        __syncthreads();

        // ---- S = x_tile @ memc^T : warp tile 16x128 ----
        float acc_s[16][4];
#pragma unroll
        for (int nb = 0; nb < 16; nb++)
#pragma unroll
            for (int q = 0; q < 4; q++) acc_s[nb][q] = 0.0f;

#pragma unroll
        for (int ks = 0; ks < 16; ks++) {
            uint32_t a0, a1, a2, a3;
            {
                int r = 16 * wid + (lane & 15);
                int colbyte = ks * 32 + ((lane >> 4) << 4);
                LDSM_X4(a0, a1, a2, a3, tile_addr(xs, r, colbyte));
            }
#pragma unroll
            for (int nb2 = 0; nb2 < 8; nb2++) {
                uint32_t d0, d1, d2, d3;
                int rn = nb2 * 16 + (lane & 7) + ((lane >> 4) << 3);
                int colbyte = ks * 32 + (((lane >> 3) & 1) << 4);
                LDSM_X4(d0, d1, d2, d3, tile_addr(ms[b], rn, colbyte));
                MMA16816(acc_s[nb2 * 2],     a0, a1, a2, a3, d0, d1);
                MMA16816(acc_s[nb2 * 2 + 1], a0, a1, a2, a3, d2, d3);
            }
        }

        // ---- online softmax ----
        float rm0 = -1e30f, rm1 = -1e30f;
#pragma unroll
        for (int nb = 0; nb < 16; nb++) {
            rm0 = fmaxf(rm0, fmaxf(acc_s[nb][0], acc_s[nb][1]));
            rm1 = fmaxf(rm1, fmaxf(acc_s[nb][2], acc_s[nb][3]));
        }
        rm0 = fmaxf(rm0, __shfl_xor_sync(0xffffffffu, rm0, 1));
        rm0 = fmaxf(rm0, __shfl_xor_sync(0xffffffffu, rm0, 2));
        rm1 = fmaxf(rm1, __shfl_xor_sync(0xffffffffu, rm1, 1));
        rm1 = fmaxf(rm1, __shfl_xor_sync(0xffffffffu, rm1, 2));

        float mn0 = fmaxf(m0, rm0), mn1 = fmaxf(m1, rm1);
        float sc0 = __expf(m0 - mn0), sc1 = __expf(m1 - mn1);
        m0 = mn0; m1 = mn1;

        uint32_t pk[16], qk[16];
        float ls0 = 0.0f, ls1 = 0.0f;
#pragma unroll
        for (int nb = 0; nb < 16; nb++) {
            float e0 = __expf(acc_s[nb][0] - mn0);
            float e1 = __expf(acc_s[nb][1] - mn0);
            float e2 = __expf(acc_s[nb][2] - mn1);
            float e3 = __expf(acc_s[nb][3] - mn1);
            ls0 += e0 + e1; ls1 += e2 + e3;
            __nv_bfloat162 h0 = __float22bfloat162_rn(make_float2(e0, e1));
            __nv_bfloat162 h1 = __float22bfloat162_rn(make_float2(e2, e3));
            pk[nb] = *reinterpret_cast<uint32_t*>(&h0);
            qk[nb] = *reinterpret_cast<uint32_t*>(&h1);
        }
        ls0 += __shfl_xor_sync(0xffffffffu, ls0, 1);
        ls0 += __shfl_xor_sync(0xffffffffu, ls0, 2);
        ls1 += __shfl_xor_sync(0xffffffffu, ls1, 1);
        ls1 += __shfl_xor_sync(0xffffffffu, ls1, 2);
        l0 = l0 * sc0 + ls0;
        l1 = l1 * sc1 + ls1;

        // rescale O
#pragma unroll
        for (int nb = 0; nb < 32; nb++) {
            acc_o[nb][0] *= sc0; acc_o[nb][1] *= sc0;
            acc_o[nb][2] *= sc1; acc_o[nb][3] *= sc1;
        }

        // ---- O += P @ memc : K=128 (mem rows), N=256 (C) ----
#pragma unroll
        for (int j = 0; j < 8; j++) {     // k16 blocks
            uint32_t a0 = pk[2 * j], a1 = qk[2 * j], a2 = pk[2 * j + 1], a3 = qk[2 * j + 1];
#pragma unroll
            for (int on = 0; on < 16; on++) {  // n16 blocks of O
                uint32_t d0, d1, d2, d3;
                int grp = lane >> 3;
                int rv = 16 * j + ((grp & 1) << 3) + (lane & 7);
                int colbyte = on * 32 + ((grp >> 1) << 4);
                LDSM_X4T(d0, d1, d2, d3, tile_addr(ms[b], rv, colbyte));
                MMA16816(acc_o[on * 2],     a0, a1, a2, a3, d0, d1);
                MMA16816(acc_o[on * 2 + 1], a0, a1, a2, a3, d2, d3);
            }
        }
        __syncthreads();
    }

    // ---- epilogue: O /= l; write cat fp32 + catb bf16, cols 256..511 ----
    float inv0 = 1.0f / l0, inv1 = 1.0f / l1;
    long r0 = row0 + 16 * wid + (lane >> 2);
    long r1 = r0 + 8;
#pragma unroll
    for (int nb = 0; nb < 32; nb++) {
        int cn = 256 + nb * 8 + (lane & 3) * 2;
        float v0 = acc_o[nb][0] * inv0, v1 = acc_o[nb][1] * inv0;
        float v2 = acc_o[nb][2] * inv1, v3 = acc_o[nb][3] * inv1;
        *(float2*)(cat + r0 * 512 + cn) = make_float2(v0, v1);
        *(float2*)(cat + r1 * 512 + cn) = make_float2(v2, v3);
        __nv_bfloat162 h0 = __float22bfloat162_rn(make_float2(v0, v1));
        __nv_bfloat162 h1 = __float22bfloat162_rn(make_float2(v2, v3));
        *(uint32_t*)(catb + r0 * 512 + cn) = *reinterpret_cast<uint32_t*>(&h0);
        *(uint32_t*)(catb + r1 * 512 + cn) = *reinterpret_cast<uint32_t*>(&h1);
    }
}

// ---------------------------------------------------------------------------
// bf16 GEMM (as R3): BM=128, BN=128, BK=64, 256 thr, warp tile 32x64.
// EPI: 2 = silu(v+bias) -> bf16 Cb ; 3 = sigmoid(v+bias) -> fp32 Cf
// ---------------------------------------------------------------------------
template<int EPI>
__global__ void __launch_bounds__(256, 2)
gemm_mma(const __nv_bfloat16* __restrict__ A, const __nv_bfloat16* __restrict__ B,
         const float* __restrict__ bias, float* __restrict__ Cf,
         __nv_bfloat16* __restrict__ Cb, int K, int ldcf, int ldcb, int c_off)
{
    extern __shared__ char dsm[];
    const uint32_t sbase = (smem_u32(dsm) + 1023) & ~1023u;
    const int tid = threadIdx.x;
    const int wid = tid >> 5, lane = tid & 31;
    const int wm = wid & 3;
    const int wn = wid >> 2;
    const long row0 = (long)blockIdx.y * 128;
    const long col0 = (long)blockIdx.x * 128;

    const uint32_t sA[2] = { sbase,         sbase + 32768 };
    const uint32_t sB[2] = { sbase + 16384, sbase + 49152 };

    float acc[2][8][4];
#pragma unroll
    for (int i = 0; i < 2; i++)
#pragma unroll
        for (int j = 0; j < 8; j++)
#pragma unroll
            for (int q = 0; q < 4; q++) acc[i][j][q] = 0.0f;

    const char* Ag = (const char*)(A + row0 * K);
    const char* Bg = (const char*)(B + col0 * K);
    const long rowb = (long)K * 2;
    const int lr = tid >> 3;
    const int lc = tid & 7;
    const int nchunks = K >> 6;

    {
#pragma unroll
        for (int j = 0; j < 4; j++) {
            int r = lr + j * 32;
            uint32_t off = (uint32_t)(r * 128) + (uint32_t)((lc ^ (r & 7)) << 4);
            CP_ASYNC16(sA[0] + off, Ag + (long)r * rowb + lc * 16);
            CP_ASYNC16(sB[0] + off, Bg + (long)r * rowb + lc * 16);
        }
        CP_COMMIT();
    }

    for (int i = 0; i < nchunks; i++) {
        const int b = i & 1;
        if (i + 1 < nchunks) {
            const long kb = (long)(i + 1) << 7;
#pragma unroll
            for (int j = 0; j < 4; j++) {
                int r = lr + j * 32;
                uint32_t off = (uint32_t)(r * 128) + (uint32_t)((lc ^ (r & 7)) << 4);
                CP_ASYNC16(sA[1 - b] + off, Ag + (long)r * rowb + kb + lc * 16);
                CP_ASYNC16(sB[1 - b] + off, Bg + (long)r * rowb + kb + lc * 16);
            }
            CP_COMMIT();
            CP_WAIT(1);
        } else {
            CP_WAIT(0);
        }
        __syncthreads();

#pragma unroll
        for (int ks = 0; ks < 4; ks++) {
            uint32_t af[2][4];
#pragma unroll
            for (int mi = 0; mi < 2; mi++) {
                int r = wm * 32 + mi * 16 + (lane & 15);
                int cch = ks * 2 + (lane >> 4);
                uint32_t addr = sA[b] + (uint32_t)(r * 128) + (uint32_t)((cch ^ (r & 7)) << 4);
                LDSM_X4(af[mi][0], af[mi][1], af[mi][2], af[mi][3], addr);
            }
            uint32_t bf[4][4];
#pragma unroll
            for (int nt = 0; nt < 4; nt++) {
                int r = wn * 64 + nt * 16 + (lane & 7) + ((lane >> 4) << 3);
                int cch = ks * 2 + ((lane >> 3) & 1);
                uint32_t addr = sB[b] + (uint32_t)(r * 128) + (uint32_t)((cch ^ (r & 7)) << 4);
                LDSM_X4(bf[nt][0], bf[nt][1], bf[nt][2], bf[nt][3], addr);
            }
#pragma unroll
            for (int mi = 0; mi < 2; mi++)
#pragma unroll
                for (int ni = 0; ni < 8; ni++) {
                    uint32_t b0 = bf[ni >> 1][(ni & 1) * 2];
                    uint32_t b1 = bf[ni >> 1][(ni & 1) * 2 + 1];
                    MMA16816(acc[mi][ni], af[mi][0], af[mi][1], af[mi][2], af[mi][3], b0, b1);
                }
        }
        __syncthreads();
    }

#pragma unroll
    for (int mi = 0; mi < 2; mi++) {
#pragma unroll
        for (int h = 0; h < 2; h++) {
            long r = row0 + wm * 32 + mi * 16 + (lane >> 2) + h * 8;
#pragma unroll
            for (int ni = 0; ni < 8; ni++) {
                int cn = (int)col0 + wn * 64 + ni * 8 + (lane & 3) * 2;
                float v0 = acc[mi][ni][h * 2];
                float v1 = acc[mi][ni][h * 2 + 1];
                v0 += bias[cn];
                v1 += bias[cn + 1];
                if (EPI == 2) {
                    v0 = v0 / (1.0f + __expf(-v0));
                    v1 = v1 / (1.0f + __expf(-v1));
                } else {
                    v0 = 1.0f / (1.0f + __expf(-v0));
                    v1 = 1.0f / (1.0f + __expf(-v1));
                }
                if (EPI == 2) {
                    __nv_bfloat162 h2 = __float22bfloat162_rn(make_float2(v0, v1));
                    *(uint32_t*)(Cb + r * ldcb + c_off + cn) = *reinterpret_cast<uint32_t*>(&h2);
                } else {
                    *(float2*)(Cf + r * ldcf + c_off + cn) = make_float2(v0, v1);
                }
            }
        }
    }
}

// ---------------------------------------------------------------------------
__global__ void convert_x(const float4* __restrict__ x4, float4* __restrict__ cat4,
                          uint2* __restrict__ xb2, uint2* __restrict__ catb2)
{
    long i = (long)blockIdx.x * 256 + threadIdx.x;
    long row = i >> 6;
    long c4 = i & 63;
    float4 v = x4[i];
    cat4[row * 128 + c4] = v;
    __nv_bfloat162 l = __float22bfloat162_rn(make_float2(v.x, v.y));
    __nv_bfloat162 h = __float22bfloat162_rn(make_float2(v.z, v.w));
    uint2 pk = make_uint2(*reinterpret_cast<uint32_t*>(&l), *reinterpret_cast<uint32_t*>(&h));
    xb2[i] = pk;
    catb2[row * 128 + c4] = pk;
}

__global__ void conv_mem(const float* __restrict__ mem, __nv_bfloat16* __restrict__ memb)
{
    int i = blockIdx.x * 256 + threadIdx.x;
    memb[i] = __float2bfloat16(mem[i]);
}

__global__ void conv_w1(const float* __restrict__ w1, __nv_bfloat16* __restrict__ w1T)
{
    int i = blockIdx.x * 256 + threadIdx.x;
    int k = i >> 10, n = i & 1023;
    w1T[n * 512 + k] = __float2bfloat16(w1[i]);
}

__global__ void conv_w2(const float* __restrict__ w2, __nv_bfloat16* __restrict__ w2T)
{
    int i = blockIdx.x * 256 + threadIdx.x;
    int f = i >> 8, c = i & 255;
    w2T[c * 1024 + f] = __float2bfloat16(w2[i]);
}

__global__ void xmean_kernel(const float* __restrict__ x, float* __restrict__ xm)
{
    int b = blockIdx.x, c = threadIdx.x;
    const float* p = x + (long)b * 1024 * 256 + c;
    float s = 0.0f;
    for (int t = 0; t < 1024; t++) s += p[t * 256];
    xm[b * 256 + c] = s * (1.0f / 1024.0f);
}

__global__ void newmem_kernel(const float* __restrict__ mem, const float* __restrict__ g,
                              const float* __restrict__ xm, float* __restrict__ outp)
{
    int idx = blockIdx.x * 256 + threadIdx.x;
    int c = idx & 255;
    float mm = mem[idx];
    float s = 0.0f;
#pragma unroll 4
    for (int b = 0; b < 64; b++) {
        float gg = g[(long)b * 262144 + idx];
        s += mm + (xm[b * 256 + c] - mm) * gg;
    }
    outp[idx] = s * (1.0f / 64.0f);
}

// ---------------------------------------------------------------------------
extern "C" void kernel_launch(void* const* d_in, const int* in_sizes, int n_in,
                              void* d_out, int out_size)
{
    const float* x      = (const float*)d_in[0];
    const float* memory = (const float*)d_in[1];
    const float* w1     = (const float*)d_in[2];
    const float* b1     = (const float*)d_in[3];
    const float* w2     = (const float*)d_in[4];
    const float* b2     = (const float*)d_in[5];

    float* out    = (float*)d_out;
    float* cat    = out;               // [65536,512]
    float* newmem = out + 33554432ll;  // [1024,256]

    __nv_bfloat16 *xb, *catb, *hb, *memb, *w1T, *w2T;
    float *gate, *xm;
    cudaGetSymbolAddress((void**)&xb, g_xb);
    cudaGetSymbolAddress((void**)&catb, g_catb);
    cudaGetSymbolAddress((void**)&hb, g_hb);
    cudaGetSymbolAddress((void**)&gate, g_gate);
    cudaGetSymbolAddress((void**)&memb, g_memb);
    cudaGetSymbolAddress((void**)&w1T, g_w1T);
    cudaGetSymbolAddress((void**)&w2T, g_w2T);
    cudaGetSymbolAddress((void**)&xm, g_xmean);

    const int SMEM_G = 1024 + 65536;          // gemm: guard + 2x(16KB+16KB)
    const int SMEM_F = 1024 + 3 * 65536;      // flash: guard + x + 2 mem bufs
    cudaFuncSetAttribute(gemm_mma<2>, cudaFuncAttributeMaxDynamicSharedMemorySize, SMEM_G);
    cudaFuncSetAttribute(gemm_mma<3>, cudaFuncAttributeMaxDynamicSharedMemorySize, SMEM_G);
    cudaFuncSetAttribute(flash_attn, cudaFuncAttributeMaxDynamicSharedMemorySize, SMEM_F);

    // conversions
    convert_x<<<16384, 256>>>((const float4*)x, (float4*)cat, (uint2*)xb, (uint2*)catb);
    conv_mem<<<1024, 256>>>(memory, memb);
    conv_w1<<<2048, 256>>>(w1, w1T);
    conv_w2<<<1024, 256>>>(w2, w2T);

    // fused G1 + softmax + G2 -> cat[:,256:512] fp32 + catb[:,256:512] bf16
    flash_attn<<<512, 256, SMEM_F>>>(xb, memb, cat, catb);

    // G3: h = silu(catb @ w1T^T + b1) -> hb bf16 [65536,1024]
    gemm_mma<2><<<dim3(8, 512), 256, SMEM_G>>>(catb, w1T, b1, nullptr, hb, 512, 0, 1024, 0);

    // G4: g = sigmoid(hb @ w2T^T + b2) -> gate fp32 [65536,256]
    gemm_mma<3><<<dim3(2, 512), 256, SMEM_G>>>(hb, w2T, b2, gate, nullptr, 1024, 256, 0, 0);

    // reductions
    xmean_kernel<<<64, 256>>>(x, xm);
    newmem_kernel<<<1024, 256>>>(memory, gate, xm, newmem);
}